// round 3
// baseline (speedup 1.0000x reference)
#include <cuda_runtime.h>
#include <math.h>

#define BATCH 16
#define SEQ   1024
#define DM    512
#define HD    64
#define DFF   2048
#define MTOT  (BATCH*SEQ)   // 16384
#define NLAYERS 4

// ---------------- scratch (static device globals; no allocation) -------------
__device__ float g_q[MTOT*HD];
__device__ float g_k[MTOT*HD];
__device__ float g_v[MTOT*HD];
__device__ float g_S[BATCH*SEQ*SEQ];      // 64 MB scores
__device__ float g_m[BATCH*SEQ];          // per-(b,key) column max
__device__ float g_rs[BATCH*SEQ];         // per-(b,key) 1/colsum
__device__ float g_head[MTOT*HD];
__device__ float g_t1[MTOT*DM];
__device__ float g_h[MTOT*DM];
__device__ float g_u[MTOT*DFF];           // 128 MB FF hidden
__device__ float g_t2[MTOT*DM];
__device__ float g_x[MTOT*DM];
__device__ float g_weff[HD*DM];

// ---------------- generic fp32 tiled GEMM: C = A@B + bias (+resid) ----------
// Row-major A[M,K], B[K,N], C[M,N]. Dims assumed multiples of tiles (true here).
template<int BM, int BN, int BK, int TM, int TN, bool RES>
__global__ __launch_bounds__((BM/TM)*(BN/TN))
void sgemm(const float* __restrict__ A, const float* __restrict__ B,
           const float* __restrict__ bias, const float* __restrict__ resid,
           float* __restrict__ C, int M, int N, int K)
{
    constexpr int NT = (BM/TM)*(BN/TN);
    __shared__ __align__(16) float As[BK][BM];
    __shared__ __align__(16) float Bs[BK][BN];
    const int tid = threadIdx.x;
    const int tx  = tid % (BN/TN);
    const int ty  = tid / (BN/TN);
    const int m0  = blockIdx.y * BM;
    const int n0  = blockIdx.x * BN;

    float acc[TM][TN];
    #pragma unroll
    for (int i = 0; i < TM; i++)
        #pragma unroll
        for (int j = 0; j < TN; j++) acc[i][j] = 0.f;

    for (int k0 = 0; k0 < K; k0 += BK) {
        #pragma unroll
        for (int i = tid; i < BM*BK; i += NT) {
            int r = i / BK, c = i % BK;
            As[c][r] = A[(size_t)(m0 + r) * K + (k0 + c)];
        }
        #pragma unroll
        for (int i = tid; i < BK*BN; i += NT) {
            int r = i / BN, c = i % BN;
            Bs[r][c] = B[(size_t)(k0 + r) * N + (n0 + c)];
        }
        __syncthreads();
        #pragma unroll
        for (int kk = 0; kk < BK; kk++) {
            float a[TM], bf[TN];
            #pragma unroll
            for (int i = 0; i < TM; i += 4)
                *(float4*)&a[i] = *(const float4*)&As[kk][ty*TM + i];
            #pragma unroll
            for (int j = 0; j < TN; j += 4)
                *(float4*)&bf[j] = *(const float4*)&Bs[kk][tx*TN + j];
            #pragma unroll
            for (int i = 0; i < TM; i++)
                #pragma unroll
                for (int j = 0; j < TN; j++)
                    acc[i][j] = fmaf(a[i], bf[j], acc[i][j]);
        }
        __syncthreads();
    }

    #pragma unroll
    for (int i = 0; i < TM; i++) {
        size_t row = (size_t)(m0 + ty*TM + i);
        #pragma unroll
        for (int j = 0; j < TN; j += 4) {
            int col = n0 + tx*TN + j;
            float4 b4 = *(const float4*)&bias[col];
            float4 o;
            o.x = acc[i][j+0] + b4.x;
            o.y = acc[i][j+1] + b4.y;
            o.z = acc[i][j+2] + b4.z;
            o.w = acc[i][j+3] + b4.w;
            if (RES) {
                float4 r4 = *(const float4*)&resid[row * N + col];
                o.x += r4.x; o.y += r4.y; o.z += r4.z; o.w += r4.w;
            }
            *(float4*)&C[row * N + col] = o;
        }
    }
}

// ---------------- scores: S[b] = (q[b] @ k[b]^T) * 0.125 --------------------
__global__ __launch_bounds__(256)
void scores_kernel(const float* __restrict__ q, const float* __restrict__ k,
                   float* __restrict__ S)
{
    __shared__ __align__(16) float QT[HD][68];  // [d][m] transposed, padded
    __shared__ __align__(16) float KT[HD][68];  // [d][n]
    const int b  = blockIdx.z;
    const int m0 = blockIdx.y * 64;
    const int n0 = blockIdx.x * 64;
    const int tid = threadIdx.x;
    const int tx = tid & 15, ty = tid >> 4;
    const float* qb = q + (size_t)b * SEQ * HD;
    const float* kb = k + (size_t)b * SEQ * HD;

    #pragma unroll
    for (int i = tid; i < 64*HD; i += 256) {
        int r = i >> 6, c = i & 63;
        QT[c][r] = qb[(size_t)(m0 + r) * HD + c];
    }
    #pragma unroll
    for (int i = tid; i < 64*HD; i += 256) {
        int r = i >> 6, c = i & 63;
        KT[c][r] = kb[(size_t)(n0 + r) * HD + c];
    }
    __syncthreads();

    float acc[4][4] = {};
    #pragma unroll 16
    for (int d = 0; d < HD; d++) {
        float a[4], bf[4];
        *(float4*)a  = *(const float4*)&QT[d][ty*4];
        *(float4*)bf = *(const float4*)&KT[d][tx*4];
        #pragma unroll
        for (int i = 0; i < 4; i++)
            #pragma unroll
            for (int j = 0; j < 4; j++)
                acc[i][j] = fmaf(a[i], bf[j], acc[i][j]);
    }

    float* Sb = S + (size_t)b * SEQ * SEQ;
    #pragma unroll
    for (int i = 0; i < 4; i++) {
        size_t row = (size_t)(m0 + ty*4 + i);
        float4 o;
        o.x = acc[i][0]*0.125f; o.y = acc[i][1]*0.125f;
        o.z = acc[i][2]*0.125f; o.w = acc[i][3]*0.125f;
        *(float4*)&Sb[row * SEQ + (n0 + tx*4)] = o;
    }
}

// ---------------- column softmax stats (softmax over q axis) ----------------
__global__ __launch_bounds__(256)
void colstats_kernel(const float* __restrict__ S, float* __restrict__ mout,
                     float* __restrict__ rsout)
{
    const int b = blockIdx.y;
    const int j = blockIdx.x * 256 + threadIdx.x;   // key index
    const float* Sb = S + (size_t)b * SEQ * SEQ;
    float m = -1e30f, s = 0.f;
    for (int i = 0; i < SEQ; i++) {
        float v = Sb[(size_t)i * SEQ + j];
        if (v > m) { s = s * __expf(m - v) + 1.f; m = v; }
        else       { s += __expf(v - m); }
    }
    mout[b*SEQ + j]  = m;
    rsout[b*SEQ + j] = 1.f / s;
}

// ---------------- head = softmax_col(S) @ v (exp fused into A load) ---------
__global__ __launch_bounds__(256)
void headv_kernel(const float* __restrict__ S, const float* __restrict__ v,
                  const float* __restrict__ mcol, const float* __restrict__ rscol,
                  float* __restrict__ head)
{
    __shared__ __align__(16) float PT[16][68];  // [k][m] transposed, padded
    __shared__ __align__(16) float Vs[16][64];  // [k][d]
    const int b  = blockIdx.y;
    const int m0 = blockIdx.x * 64;
    const int tid = threadIdx.x;
    const int tx = tid & 15, ty = tid >> 4;
    const float* Sb = S + (size_t)b * SEQ * SEQ;
    const float* vb = v + (size_t)b * SEQ * HD;
    const float* mb = mcol  + b*SEQ;
    const float* rb = rscol + b*SEQ;

    float acc[4][4] = {};
    for (int k0 = 0; k0 < SEQ; k0 += 16) {
        #pragma unroll
        for (int i = tid; i < 64*16; i += 256) {
            int r = i >> 4, c = i & 15;
            int kg = k0 + c;
            PT[c][r] = __expf(Sb[(size_t)(m0 + r) * SEQ + kg] - mb[kg]) * rb[kg];
        }
        #pragma unroll
        for (int i = tid; i < 16*64; i += 256) {
            int r = i >> 6, c = i & 63;
            Vs[r][c] = vb[(size_t)(k0 + r) * HD + c];
        }
        __syncthreads();
        #pragma unroll
        for (int kk = 0; kk < 16; kk++) {
            float a[4], bf[4];
            *(float4*)a  = *(const float4*)&PT[kk][ty*4];
            *(float4*)bf = *(const float4*)&Vs[kk][tx*4];
            #pragma unroll
            for (int i = 0; i < 4; i++)
                #pragma unroll
                for (int j = 0; j < 4; j++)
                    acc[i][j] = fmaf(a[i], bf[j], acc[i][j]);
        }
        __syncthreads();
    }

    #pragma unroll
    for (int i = 0; i < 4; i++) {
        size_t row = (size_t)(b*SEQ + m0 + ty*4 + i);
        float4 o;
        o.x = acc[i][0]; o.y = acc[i][1]; o.z = acc[i][2]; o.w = acc[i][3];
        *(float4*)&head[row * HD + (tx*4)] = o;
    }
}

// ---------------- LayerNorm (per-row, biased variance, eps=1e-5) ------------
__global__ __launch_bounds__(128)
void ln_kernel(const float* __restrict__ in, const float* __restrict__ gamma,
               const float* __restrict__ beta, float* __restrict__ out)
{
    __shared__ float red[8];
    const int row = blockIdx.x;
    const int tid = threadIdx.x;             // 128 threads, 4 floats each
    float4 v = ((const float4*)(in + (size_t)row * DM))[tid];
    float s  = v.x + v.y + v.z + v.w;
    float ss = v.x*v.x + v.y*v.y + v.z*v.z + v.w*v.w;
    #pragma unroll
    for (int o = 16; o > 0; o >>= 1) {
        s  += __shfl_xor_sync(0xffffffffu, s,  o);
        ss += __shfl_xor_sync(0xffffffffu, ss, o);
    }
    const int warp = tid >> 5;
    if ((tid & 31) == 0) { red[warp] = s; red[4 + warp] = ss; }
    __syncthreads();
    s  = red[0] + red[1] + red[2] + red[3];
    ss = red[4] + red[5] + red[6] + red[7];
    float mu  = s * (1.f / DM);
    float var = ss * (1.f / DM) - mu * mu;
    float inv = rsqrtf(var + 1e-5f);
    float4 g = ((const float4*)gamma)[tid];
    float4 b = ((const float4*)beta)[tid];
    float4 o;
    o.x = (v.x - mu) * inv * g.x + b.x;
    o.y = (v.y - mu) * inv * g.y + b.y;
    o.z = (v.z - mu) * inv * g.z + b.z;
    o.w = (v.w - mu) * inv * g.w + b.w;
    ((float4*)(out + (size_t)row * DM))[tid] = o;
}

// ---------------- W_eff[r,c] = sum_h wo[64h+r, c] ---------------------------
__global__ void weff_kernel(const float* __restrict__ wo, float* __restrict__ weff)
{
    int idx = blockIdx.x * 256 + threadIdx.x;
    if (idx < HD * DM) {
        int r = idx / DM, c = idx % DM;
        float s = 0.f;
        #pragma unroll
        for (int h = 0; h < 8; h++) s += wo[(size_t)(h*HD + r) * DM + c];
        weff[idx] = s;
    }
}

// ---------------- host orchestration ----------------------------------------
extern "C" void kernel_launch(void* const* d_in, const int* in_sizes, int n_in,
                              void* d_out, int out_size)
{
    (void)in_sizes; (void)n_in; (void)out_size;
    const float* x   = (const float*)d_in[0];
    const float* wq  = (const float*)d_in[1];
    const float* bq  = (const float*)d_in[2];
    const float* wk  = (const float*)d_in[3];
    const float* bk  = (const float*)d_in[4];
    const float* wv  = (const float*)d_in[5];
    const float* bv  = (const float*)d_in[6];
    const float* wo  = (const float*)d_in[7];
    const float* bo  = (const float*)d_in[8];
    const float* lng = (const float*)d_in[9];
    const float* lnb = (const float*)d_in[10];
    const float* w1  = (const float*)d_in[11];
    const float* b1  = (const float*)d_in[12];
    const float* w2  = (const float*)d_in[13];
    const float* b2  = (const float*)d_in[14];
    float* out = (float*)d_out;

    float *q, *k, *v, *S, *m, *rs, *head, *t1, *h, *u, *t2, *xb, *weff;
    cudaGetSymbolAddress((void**)&q,    g_q);
    cudaGetSymbolAddress((void**)&k,    g_k);
    cudaGetSymbolAddress((void**)&v,    g_v);
    cudaGetSymbolAddress((void**)&S,    g_S);
    cudaGetSymbolAddress((void**)&m,    g_m);
    cudaGetSymbolAddress((void**)&rs,   g_rs);
    cudaGetSymbolAddress((void**)&head, g_head);
    cudaGetSymbolAddress((void**)&t1,   g_t1);
    cudaGetSymbolAddress((void**)&h,    g_h);
    cudaGetSymbolAddress((void**)&u,    g_u);
    cudaGetSymbolAddress((void**)&t2,   g_t2);
    cudaGetSymbolAddress((void**)&xb,   g_x);
    cudaGetSymbolAddress((void**)&weff, g_weff);

    weff_kernel<<<(HD*DM + 255)/256, 256>>>(wo, weff);

    const float* xin = x;
    for (int L = 0; L < NLAYERS; L++) {
        // QKV projections: [16384,64] = x @ w* + b*   (K=512)
        dim3 gqkv(HD/64, MTOT/128);
        sgemm<128,64,8,8,4,false><<<gqkv, 256>>>(xin, wq, bq, nullptr, q, MTOT, HD, DM);
        sgemm<128,64,8,8,4,false><<<gqkv, 256>>>(xin, wk, bk, nullptr, k, MTOT, HD, DM);
        sgemm<128,64,8,8,4,false><<<gqkv, 256>>>(xin, wv, bv, nullptr, v, MTOT, HD, DM);

        // scores, column softmax stats, head = P @ v
        scores_kernel<<<dim3(SEQ/64, SEQ/64, BATCH), 256>>>(q, k, S);
        colstats_kernel<<<dim3(SEQ/256, BATCH), 256>>>(S, m, rs);
        headv_kernel<<<dim3(SEQ/64, BATCH), 256>>>(S, v, m, rs, head);

        // O projection via W_eff (K=64) + bias + residual x, then LN -> h
        sgemm<128,128,8,8,8,true><<<dim3(DM/128, MTOT/128), 256>>>(head, weff, bo, xin, t1, MTOT, DM, HD);
        ln_kernel<<<MTOT, 128>>>(t1, lng, lnb, h);

        // FF: u = h@w1+b1 ; t2 = u@w2+b2+h ; x_next = LN(t2)
        sgemm<128,128,8,8,8,false><<<dim3(DFF/128, MTOT/128), 256>>>(h, w1, b1, nullptr, u, MTOT, DFF, DM);
        sgemm<128,128,8,8,8,true ><<<dim3(DM/128,  MTOT/128), 256>>>(u, w2, b2, h, t2, MTOT, DM, DFF);
        ln_kernel<<<MTOT, 128>>>(t2, lng, lnb, (L == NLAYERS-1) ? out : xb);

        xin = xb;
    }
}

// round 4
// speedup vs baseline: 3.7553x; 3.7553x over previous
#include <cuda_runtime.h>
#include <math.h>
#include <stdint.h>

#define BATCH 16
#define SEQ   1024
#define DM    512
#define HD    64
#define DFF   2048
#define MTOT  (BATCH*SEQ)   // 16384
#define NLAYERS 4

// ---------------- scratch (static device globals; no allocation) -------------
__device__ float g_qkv[MTOT*192];                 // q|k|v packed per row
__device__ float g_E[(size_t)BATCH*SEQ*SEQ];      // exp(scores), 64 MB
__device__ float g_rs[MTOT];                      // 1/colsum per (b,key)
__device__ float g_v[MTOT*HD];                    // v * rs (tf32-rounded)
__device__ float g_head[MTOT*HD];
__device__ float g_t1[MTOT*DM];
__device__ float g_h[MTOT*DM];
__device__ float g_u[(size_t)MTOT*DFF];           // 128 MB
__device__ float g_t2[MTOT*DM];
__device__ float g_x[MTOT*DM];                    // trunk (tf32-rounded)
__device__ float g_x0[MTOT*DM];                   // rounded copy of input x
__device__ float g_wqkv[DM*192];
__device__ float g_bqkv[192];
__device__ float g_weff[HD*DM];
__device__ float g_w1c[DM*DFF];
__device__ float g_w2c[DFF*DM];

__device__ __forceinline__ float tf32r(float x) {
    uint32_t u; asm("cvt.rna.tf32.f32 %0, %1;" : "=r"(u) : "f"(x));
    return __uint_as_float(u);
}
__device__ __forceinline__ void cpasync16(uint32_t s, const void* g) {
    asm volatile("cp.async.cg.shared.global [%0], [%1], 16;" :: "r"(s), "l"(g));
}

// ---------------- tf32 tensor-core GEMM --------------------------------------
// C[M,ldc] = A[M,lda-strided] @ B + bias (+resid), optional exp(x/8), optional
// tf32-round of output. B normal: B[k,n] row-major (ldb = row stride).
// BTRANS: B provided as [n,k] row-major (scores: B = K-matrix).
// Batched via blockIdx.z with element strides sA/sB/sC.
template<int BN, bool BTRANS, bool HASBIAS, bool RES, bool EXPSC, bool CVT>
__global__ __launch_bounds__(256, 2)
void mm_tc(const float* __restrict__ A, const float* __restrict__ Bm,
           const float* __restrict__ bias, const float* __restrict__ resid,
           float* __restrict__ C, int K, int lda, int ldb, int ldc,
           long long sA, long long sB, long long sC)
{
    constexpr int BM = 128, BK = 16;
    constexpr int WN = BN / 2;       // warp n-extent (2 warp cols)
    constexpr int NF = WN / 8;       // n-fragments per warp
    constexpr int BSR = BTRANS ? BN : BK;
    constexpr int BSC = BTRANS ? (BK + 4) : (BN + 8);
    __shared__ float As[2][BM][BK + 4];
    __shared__ float Bs[2][BSR][BSC];

    const int tid  = threadIdx.x;
    const int lane = tid & 31, warp = tid >> 5;
    const int wr = warp & 3, wc = warp >> 2;
    const int g = lane >> 2, q = lane & 3;
    const int m0 = blockIdx.y * BM;
    const int n0 = blockIdx.x * BN;
    const int z  = blockIdx.z;
    const float* Ab = A  + (size_t)z * sA;
    const float* Bb = Bm + (size_t)z * sB;

    auto stage = [&](int t, int s) {
        int k0 = t * BK;
        #pragma unroll
        for (int p = 0; p < 2; p++) {                 // A: 128x16 = 512 f4
            int c = tid + p * 256;
            int r = c >> 2, kc = (c & 3) << 2;
            uint32_t sa = (uint32_t)__cvta_generic_to_shared(&As[s][r][kc]);
            cpasync16(sa, Ab + (size_t)(m0 + r) * lda + k0 + kc);
        }
        if (BTRANS) {
            #pragma unroll
            for (int p = 0; p < (BN * BK) / 1024; p++) {
                int c = tid + p * 256;
                int r = c >> 2, kc = (c & 3) << 2;
                uint32_t sa = (uint32_t)__cvta_generic_to_shared(&Bs[s][r][kc]);
                cpasync16(sa, Bb + (size_t)(n0 + r) * ldb + k0 + kc);
            }
        } else {
            constexpr int CPR = BN / 4;               // f4 chunks per B row
            #pragma unroll
            for (int p = 0; p < (BK * BN) / 1024; p++) {
                int c = tid + p * 256;
                int r = c / CPR, nc = (c % CPR) << 2;
                uint32_t sa = (uint32_t)__cvta_generic_to_shared(&Bs[s][r][nc]);
                cpasync16(sa, Bb + (size_t)(k0 + r) * ldb + n0 + nc);
            }
        }
        asm volatile("cp.async.commit_group;");
    };

    float acc[2][NF][4];
    #pragma unroll
    for (int i = 0; i < 2; i++)
        #pragma unroll
        for (int j = 0; j < NF; j++)
            #pragma unroll
            for (int c = 0; c < 4; c++) acc[i][j][c] = 0.f;

    const int mw = wr * 32;
    const int nw = wc * WN;
    const int T = K / BK;

    stage(0, 0);
    for (int t = 0; t < T; t++) {
        if (t + 1 < T) { stage(t + 1, (t + 1) & 1); asm volatile("cp.async.wait_group 1;"); }
        else           { asm volatile("cp.async.wait_group 0;"); }
        __syncthreads();
        const int s = t & 1;
        #pragma unroll
        for (int ks = 0; ks < BK; ks += 8) {
            uint32_t af[2][4];
            #pragma unroll
            for (int i = 0; i < 2; i++) {
                af[i][0] = __float_as_uint(As[s][mw + i*16 + g    ][ks + q    ]);
                af[i][1] = __float_as_uint(As[s][mw + i*16 + g + 8][ks + q    ]);
                af[i][2] = __float_as_uint(As[s][mw + i*16 + g    ][ks + q + 4]);
                af[i][3] = __float_as_uint(As[s][mw + i*16 + g + 8][ks + q + 4]);
            }
            uint32_t bf[NF][2];
            #pragma unroll
            for (int j = 0; j < NF; j++) {
                int n = nw + j * 8 + g;
                if (BTRANS) {
                    bf[j][0] = __float_as_uint(Bs[s][n][ks + q    ]);
                    bf[j][1] = __float_as_uint(Bs[s][n][ks + q + 4]);
                } else {
                    bf[j][0] = __float_as_uint(Bs[s][ks + q    ][n]);
                    bf[j][1] = __float_as_uint(Bs[s][ks + q + 4][n]);
                }
            }
            #pragma unroll
            for (int i = 0; i < 2; i++)
                #pragma unroll
                for (int j = 0; j < NF; j++)
                    asm volatile(
                        "mma.sync.aligned.m16n8k8.row.col.f32.tf32.tf32.f32 "
                        "{%0,%1,%2,%3}, {%4,%5,%6,%7}, {%8,%9}, {%0,%1,%2,%3};"
                        : "+f"(acc[i][j][0]), "+f"(acc[i][j][1]),
                          "+f"(acc[i][j][2]), "+f"(acc[i][j][3])
                        : "r"(af[i][0]), "r"(af[i][1]), "r"(af[i][2]), "r"(af[i][3]),
                          "r"(bf[j][0]), "r"(bf[j][1]));
        }
        __syncthreads();
    }

    float* Cb = C + (size_t)z * sC;
    #pragma unroll
    for (int i = 0; i < 2; i++) {
        #pragma unroll
        for (int j = 0; j < NF; j++) {
            int col = n0 + nw + j * 8 + 2 * q;
            #pragma unroll
            for (int hh = 0; hh < 2; hh++) {
                int row = m0 + mw + i * 16 + g + hh * 8;
                float v0 = acc[i][j][hh * 2 + 0];
                float v1 = acc[i][j][hh * 2 + 1];
                if (EXPSC)  { v0 = __expf(v0 * 0.125f); v1 = __expf(v1 * 0.125f); }
                if (HASBIAS){ v0 += bias[col]; v1 += bias[col + 1]; }
                if (RES) {
                    v0 += resid[(size_t)row * ldc + col];
                    v1 += resid[(size_t)row * ldc + col + 1];
                }
                if (CVT) { v0 = tf32r(v0); v1 = tf32r(v1); }
                *(float2*)&Cb[(size_t)row * ldc + col] = make_float2(v0, v1);
            }
        }
    }
}

// ---------------- column sums of E: rs = 1/sum_i E[i,j] ----------------------
__global__ __launch_bounds__(256)
void colsum_k(const float* __restrict__ E, float* __restrict__ rs)
{
    __shared__ float sm[8][33];
    const int b = blockIdx.y, j0 = blockIdx.x * 32;
    const int jj = threadIdx.x & 31, ch = threadIdx.x >> 5;
    const float* Eb = E + (size_t)b * SEQ * SEQ;
    float s = 0.f;
    #pragma unroll 4
    for (int i = ch; i < SEQ; i += 8)
        s += Eb[(size_t)i * SEQ + j0 + jj];
    sm[ch][jj] = s;
    __syncthreads();
    if (ch == 0) {
        float t = 0.f;
        #pragma unroll
        for (int r = 0; r < 8; r++) t += sm[r][jj];
        rs[b * SEQ + j0 + jj] = 1.f / t;
    }
}

// ---------------- v' = v * rs (tf32-rounded) ---------------------------------
__global__ void scalev_k(const float* __restrict__ qkv, const float* __restrict__ rs,
                         float* __restrict__ vout)
{
    int idx = blockIdx.x * 256 + threadIdx.x;   // one float4 each
    int row = idx >> 4;
    int c4  = (idx & 15) << 2;
    float r = rs[row];
    float4 v = *(const float4*)&qkv[(size_t)row * 192 + 128 + c4];
    v.x = tf32r(v.x * r); v.y = tf32r(v.y * r);
    v.z = tf32r(v.z * r); v.w = tf32r(v.w * r);
    *(float4*)&vout[(size_t)row * 64 + c4] = v;
}

// ---------------- LayerNorm -------------------------------------------------
template<bool CVT>
__global__ __launch_bounds__(128)
void ln_kernel(const float* __restrict__ in, const float* __restrict__ gamma,
               const float* __restrict__ beta, float* __restrict__ out)
{
    __shared__ float red[8];
    const int row = blockIdx.x;
    const int tid = threadIdx.x;
    float4 v = ((const float4*)(in + (size_t)row * DM))[tid];
    float s  = v.x + v.y + v.z + v.w;
    float ss = v.x*v.x + v.y*v.y + v.z*v.z + v.w*v.w;
    #pragma unroll
    for (int o = 16; o > 0; o >>= 1) {
        s  += __shfl_xor_sync(0xffffffffu, s,  o);
        ss += __shfl_xor_sync(0xffffffffu, ss, o);
    }
    const int warp = tid >> 5;
    if ((tid & 31) == 0) { red[warp] = s; red[4 + warp] = ss; }
    __syncthreads();
    s  = red[0] + red[1] + red[2] + red[3];
    ss = red[4] + red[5] + red[6] + red[7];
    float mu  = s * (1.f / DM);
    float var = ss * (1.f / DM) - mu * mu;
    float inv = rsqrtf(var + 1e-5f);
    float4 g = ((const float4*)gamma)[tid];
    float4 b = ((const float4*)beta)[tid];
    float4 o;
    o.x = (v.x - mu) * inv * g.x + b.x;
    o.y = (v.y - mu) * inv * g.y + b.y;
    o.z = (v.z - mu) * inv * g.z + b.z;
    o.w = (v.w - mu) * inv * g.w + b.w;
    if (CVT) { o.x = tf32r(o.x); o.y = tf32r(o.y); o.z = tf32r(o.z); o.w = tf32r(o.w); }
    ((float4*)(out + (size_t)row * DM))[tid] = o;
}

// ---------------- prep kernels ----------------------------------------------
__global__ void prep_wqkv(const float* wq, const float* wk, const float* wv,
                          const float* bq, const float* bk, const float* bv,
                          float* w, float* bias)
{
    int idx = blockIdx.x * 256 + threadIdx.x;
    if (idx < DM * 192) {
        int r = idx / 192, c = idx % 192;
        float v = (c < 64) ? wq[r*64 + c] : (c < 128 ? wk[r*64 + c - 64] : wv[r*64 + c - 128]);
        w[idx] = tf32r(v);
    }
    if (idx < 192)
        bias[idx] = (idx < 64) ? bq[idx] : (idx < 128 ? bk[idx - 64] : bv[idx - 128]);
}

__global__ void prep_weff(const float* __restrict__ wo, float* __restrict__ weff)
{
    int idx = blockIdx.x * 256 + threadIdx.x;
    if (idx < HD * DM) {
        int r = idx / DM, c = idx % DM;
        float s = 0.f;
        #pragma unroll
        for (int h = 0; h < 8; h++) s += wo[(size_t)(h*HD + r) * DM + c];
        weff[idx] = tf32r(s);
    }
}

__global__ void cvt_copy(const float* __restrict__ in, float* __restrict__ out)
{
    int idx = blockIdx.x * 256 + threadIdx.x;   // one float4 each; grid sized exactly
    float4 v = ((const float4*)in)[idx];
    v.x = tf32r(v.x); v.y = tf32r(v.y); v.z = tf32r(v.z); v.w = tf32r(v.w);
    ((float4*)out)[idx] = v;
}

// ---------------- host orchestration ----------------------------------------
extern "C" void kernel_launch(void* const* d_in, const int* in_sizes, int n_in,
                              void* d_out, int out_size)
{
    (void)in_sizes; (void)n_in; (void)out_size;
    const float* x   = (const float*)d_in[0];
    const float* wq  = (const float*)d_in[1];
    const float* bq  = (const float*)d_in[2];
    const float* wk  = (const float*)d_in[3];
    const float* bk  = (const float*)d_in[4];
    const float* wv  = (const float*)d_in[5];
    const float* bv  = (const float*)d_in[6];
    const float* wo  = (const float*)d_in[7];
    const float* bo  = (const float*)d_in[8];
    const float* lng = (const float*)d_in[9];
    const float* lnb = (const float*)d_in[10];
    const float* w1  = (const float*)d_in[11];
    const float* b1  = (const float*)d_in[12];
    const float* w2  = (const float*)d_in[13];
    const float* b2  = (const float*)d_in[14];
    float* out = (float*)d_out;

    float *qkv, *E, *rs, *vv, *head, *t1, *h, *u, *t2, *xb, *x0;
    float *wqkvD, *bqkvD, *weffD, *w1c, *w2c;
    cudaGetSymbolAddress((void**)&qkv,  g_qkv);
    cudaGetSymbolAddress((void**)&E,    g_E);
    cudaGetSymbolAddress((void**)&rs,   g_rs);
    cudaGetSymbolAddress((void**)&vv,   g_v);
    cudaGetSymbolAddress((void**)&head, g_head);
    cudaGetSymbolAddress((void**)&t1,   g_t1);
    cudaGetSymbolAddress((void**)&h,    g_h);
    cudaGetSymbolAddress((void**)&u,    g_u);
    cudaGetSymbolAddress((void**)&t2,   g_t2);
    cudaGetSymbolAddress((void**)&xb,   g_x);
    cudaGetSymbolAddress((void**)&x0,   g_x0);
    cudaGetSymbolAddress((void**)&wqkvD, g_wqkv);
    cudaGetSymbolAddress((void**)&bqkvD, g_bqkv);
    cudaGetSymbolAddress((void**)&weffD, g_weff);
    cudaGetSymbolAddress((void**)&w1c,  g_w1c);
    cudaGetSymbolAddress((void**)&w2c,  g_w2c);

    // prep: pack/round weights, round input x
    prep_wqkv<<<(DM*192 + 255)/256, 256>>>(wq, wk, wv, bq, bk, bv, wqkvD, bqkvD);
    prep_weff<<<(HD*DM + 255)/256, 256>>>(wo, weffD);
    cvt_copy<<<(DM*DFF/4)/256, 256>>>(w1, w1c);
    cvt_copy<<<(DFF*DM/4)/256, 256>>>(w2, w2c);
    cvt_copy<<<((size_t)MTOT*DM/4)/256, 256>>>(x, x0);

    const float* xinA = x0;   // tf32-rounded trunk (GEMM A input)
    const float* xinR = x;    // residual (raw on layer 0)

    for (int L = 0; L < NLAYERS; L++) {
        // fused QKV: [16384,192] = x @ Wqkv + bqkv   (CVT out)
        mm_tc<64, false, true, false, false, true><<<dim3(3, 128, 1), 256>>>(
            xinA, wqkvD, bqkvD, nullptr, qkv, DM, DM, 192, 192, 0, 0, 0);

        // E = exp(q @ k^T / 8) per batch  (CVT out)
        mm_tc<128, true, false, false, true, true><<<dim3(8, 8, 16), 256>>>(
            qkv, qkv + 64, nullptr, nullptr, E, HD, 192, 192, SEQ,
            (long long)SEQ * 192, (long long)SEQ * 192, (long long)SEQ * SEQ);

        // column sums -> rs ; v' = v * rs
        colsum_k<<<dim3(SEQ/32, BATCH), 256>>>(E, rs);
        scalev_k<<<(MTOT * 16) / 256, 256>>>(qkv, rs, vv);

        // head = E @ v' per batch  (CVT out)
        mm_tc<64, false, false, false, false, true><<<dim3(1, 8, 16), 256>>>(
            E, vv, nullptr, nullptr, head, SEQ, SEQ, HD, HD,
            (long long)SEQ * SEQ, (long long)SEQ * HD, (long long)SEQ * HD);

        // t1 = head @ weff + bo + x ; h = LN(t1) (CVT)
        mm_tc<128, false, true, true, false, false><<<dim3(4, 128, 1), 256>>>(
            head, weffD, bo, xinR, t1, HD, HD, DM, DM, 0, 0, 0);
        ln_kernel<true><<<MTOT, 128>>>(t1, lng, lnb, h);

        // FF: u = h@w1+b1 (CVT) ; t2 = u@w2+b2+h ; x_next = LN(t2)
        mm_tc<128, false, true, false, false, true><<<dim3(16, 128, 1), 256>>>(
            h, w1c, b1, nullptr, u, DM, DM, DFF, DFF, 0, 0, 0);
        mm_tc<128, false, true, true, false, false><<<dim3(4, 128, 1), 256>>>(
            u, w2c, b2, h, t2, DFF, DFF, DM, DM, 0, 0, 0);
        if (L == NLAYERS - 1)
            ln_kernel<false><<<MTOT, 128>>>(t2, lng, lnb, out);
        else
            ln_kernel<true><<<MTOT, 128>>>(t2, lng, lnb, xb);

        xinA = xb;
        xinR = xb;
    }
}